// round 2
// baseline (speedup 1.0000x reference)
#include <cuda_runtime.h>

// ---------------------------------------------------------------------------
// HybridGCNGraphSAGE: N=100000 nodes, E=1250000 edges, all feature dims = 64.
//
//  - edge_index dtype (int32 vs int64) detected at runtime each call.
//  - Build CSR-by-dst every call (deg -> 1-block scan -> atomic bin fill).
//  - PULL aggregation (no float atomics): warp-per-node, fused GCN+SAGE walk.
//  - GCN norm factored: out_i = dinv_i * (sum_{src} hd[src] + hd[i]) + b,
//    with hd = (x@W) * dinv precomputed in the GEMM kernels.
//  - Per-node GEMMs as 64-node x 64-col smem tile kernels (256 thr, 4x4
//    micro-tile), multiple matvec "phases" reusing the same smem.
//  - Final kernel fuses SAGE layer-2 linear + both LayerNorms + concat-proj.
// ---------------------------------------------------------------------------

#define NMAX 100000
#define EMAX 1250000

__device__ int   g_is64;
__device__ int   g_deg[NMAX];
__device__ int   g_rowptr[NMAX + 1];
__device__ int   g_cursor[NMAX];
__device__ int   g_csr[EMAX];
__device__ float g_dinv[NMAX];
__device__ alignas(16) float g_bufA[NMAX * 64];  // hd1, then hd2
__device__ alignas(16) float g_bufB[NMAX * 64];  // g1 (relu'd GCN layer1), then g2
__device__ alignas(16) float g_bufC[NMAX * 64];  // sage mean1, then mean2
__device__ alignas(16) float g_bufD[NMAX * 64];  // s1 (relu'd SAGE layer1)

// --------------------------- dtype detection --------------------------------
// int64 edge values are < 2^31, so every odd 32-bit word of the first 2048
// int64s is zero. int32 edge data puts random node ids there instead.
__global__ void k_detect(const unsigned int* __restrict__ w, int e) {
    __shared__ int any;
    if (threadIdx.x == 0) any = 0;
    __syncthreads();
    int limit = 2 * e; if (limit > 4096) limit = 4096;
    for (int i = 1 + 2 * (int)threadIdx.x; i < limit; i += 2 * blockDim.x)
        if (w[i] != 0u) any = 1;
    __syncthreads();
    if (threadIdx.x == 0) g_is64 = (any == 0) ? 1 : 0;
}

__device__ __forceinline__ int edge_at(const void* ei, int idx) {
    if (g_is64) return (int)((const long long*)ei)[idx];
    return ((const int*)ei)[idx];
}

// ------------------------------- CSR build ---------------------------------

__global__ void k_zero(int n) {
    int i = blockIdx.x * blockDim.x + threadIdx.x;
    if (i < n) g_deg[i] = 0;
}

__global__ void k_deg(const void* __restrict__ ei, int e) {
    int i = blockIdx.x * blockDim.x + threadIdx.x;
    if (i < e) {
        int d = edge_at(ei, e + i);
        atomicAdd(&g_deg[d], 1);
    }
}

// Single-block exclusive scan: row_ptr + cursor copy.
__global__ __launch_bounds__(1024) void k_scan(int n) {
    __shared__ int part[1024];
    int t = threadIdx.x;
    int C = (n + 1023) >> 10;
    int lo = t * C;
    int hi = lo + C; if (hi > n) hi = n;
    if (lo > n) lo = n;
    int s = 0;
    for (int i = lo; i < hi; i++) s += g_deg[i];
    part[t] = s;
    __syncthreads();
    for (int off = 1; off < 1024; off <<= 1) {
        int v = (t >= off) ? part[t - off] : 0;
        __syncthreads();
        part[t] += v;
        __syncthreads();
    }
    int run = (t == 0) ? 0 : part[t - 1];
    for (int i = lo; i < hi; i++) {
        g_rowptr[i] = run;
        g_cursor[i] = run;
        run += g_deg[i];
    }
    if (hi == n) g_rowptr[n] = run;
}

__global__ void k_fill(const void* __restrict__ ei, int e) {
    int i = blockIdx.x * blockDim.x + threadIdx.x;
    if (i < e) {
        int s = edge_at(ei, i);
        int d = edge_at(ei, e + i);
        int pos = atomicAdd(&g_cursor[d], 1);
        g_csr[pos] = s;
    }
}

// ---------------------------- tile GEMM helpers -----------------------------

__device__ __forceinline__ void load_w(float (*Ws)[64], const float* __restrict__ W) {
    float4* d = reinterpret_cast<float4*>(&Ws[0][0]);
    const float4* s = reinterpret_cast<const float4*>(W);
    for (int i = threadIdx.x; i < 1024; i += 256) d[i] = s[i];
}

__device__ __forceinline__ void load_in(float (*In)[65], const float* __restrict__ src,
                                        int base, int n) {
    for (int i = threadIdx.x; i < 1024; i += 256) {
        int r = i >> 4, c = (i & 15) << 2;
        float4 v = make_float4(0.f, 0.f, 0.f, 0.f);
        int node = base + r;
        if (node < n) v = *reinterpret_cast<const float4*>(src + node * 64 + c);
        In[r][c] = v.x; In[r][c + 1] = v.y; In[r][c + 2] = v.z; In[r][c + 3] = v.w;
    }
}

__device__ __forceinline__ void mm_acc(float (*In)[65], float (*Ws)[64],
                                       float acc[4][4], int tx, int ty) {
#pragma unroll 8
    for (int k = 0; k < 64; k++) {
        float a0 = In[ty * 4 + 0][k];
        float a1 = In[ty * 4 + 1][k];
        float a2 = In[ty * 4 + 2][k];
        float a3 = In[ty * 4 + 3][k];
        float4 w = *reinterpret_cast<float4*>(&Ws[k][tx * 4]);
        acc[0][0] += a0 * w.x; acc[0][1] += a0 * w.y; acc[0][2] += a0 * w.z; acc[0][3] += a0 * w.w;
        acc[1][0] += a1 * w.x; acc[1][1] += a1 * w.y; acc[1][2] += a1 * w.z; acc[1][3] += a1 * w.w;
        acc[2][0] += a2 * w.x; acc[2][1] += a2 * w.y; acc[2][2] += a2 * w.z; acc[2][3] += a2 * w.w;
        acc[3][0] += a3 * w.x; acc[3][1] += a3 * w.y; acc[3][2] += a3 * w.z; acc[3][3] += a3 * w.w;
    }
}

__device__ __forceinline__ void ln_rows(float (*In)[65], const float* __restrict__ gma,
                                        const float* __restrict__ bta) {
    int t = threadIdx.x;
    if (t < 64) {
        float s = 0.f, sq = 0.f;
#pragma unroll 8
        for (int k = 0; k < 64; k++) { float v = In[t][k]; s += v; sq += v * v; }
        float mu = s * 0.015625f;
        float var = sq * 0.015625f - mu * mu;
        float rs = rsqrtf(var + 1e-5f);
#pragma unroll 8
        for (int k = 0; k < 64; k++) In[t][k] = (In[t][k] - mu) * rs * gma[k] + bta[k];
    }
}

// hd1 = (x @ gcn_w1) * dinv   ; also materialize dinv[]
__global__ __launch_bounds__(256) void k_h1(const float* __restrict__ x,
                                            const float* __restrict__ w1, int n) {
    __shared__ alignas(16) float Ws[64][64];
    __shared__ alignas(16) float In[64][65];
    int base = blockIdx.x * 64;
    load_w(Ws, w1);
    load_in(In, x, base, n);
    __syncthreads();
    int tx = threadIdx.x & 15, ty = threadIdx.x >> 4;
    float acc[4][4] = {};
    mm_acc(In, Ws, acc, tx, ty);
#pragma unroll
    for (int i = 0; i < 4; i++) {
        int node = base + ty * 4 + i;
        if (node < n) {
            float dv = rsqrtf((float)g_deg[node] + 1.f);
            if (tx == 0) g_dinv[node] = dv;
            float4 v = make_float4(acc[i][0] * dv, acc[i][1] * dv, acc[i][2] * dv, acc[i][3] * dv);
            *reinterpret_cast<float4*>(&g_bufA[node * 64 + tx * 4]) = v;
        }
    }
}

// Fused pull aggregation (GCN + SAGE share the edge walk), warp-per-node.
template <bool LAYER2>
__global__ __launch_bounds__(256) void k_pull(const float* __restrict__ xsrc,
                                              const float* __restrict__ bias, int n) {
    int lane = threadIdx.x & 31;
    int i = (blockIdx.x * 256 + threadIdx.x) >> 5;
    if (i >= n) return;
    const float2* __restrict__ tg = reinterpret_cast<const float2*>(g_bufA);
    const float2* __restrict__ ts = LAYER2 ? reinterpret_cast<const float2*>(g_bufD)
                                           : reinterpret_cast<const float2*>(xsrc);
    int beg = g_rowptr[i], end = g_rowptr[i + 1];
    float sgx = 0.f, sgy = 0.f, ssx = 0.f, ssy = 0.f;
    int e = beg;
    for (; e + 2 <= end; e += 2) {
        int s0 = g_csr[e], s1 = g_csr[e + 1];
        float2 h0 = tg[s0 * 32 + lane];
        float2 h1 = tg[s1 * 32 + lane];
        float2 x0 = ts[s0 * 32 + lane];
        float2 x1 = ts[s1 * 32 + lane];
        sgx += h0.x + h1.x; sgy += h0.y + h1.y;
        ssx += x0.x + x1.x; ssy += x0.y + x1.y;
    }
    if (e < end) {
        int s0 = g_csr[e];
        float2 h0 = tg[s0 * 32 + lane];
        float2 x0 = ts[s0 * 32 + lane];
        sgx += h0.x; sgy += h0.y; ssx += x0.x; ssy += x0.y;
    }
    float dv = g_dinv[i];
    float2 self = tg[i * 32 + lane];
    float2 bv = reinterpret_cast<const float2*>(bias)[lane];
    float gx = (sgx + self.x) * dv + bv.x;
    float gy = (sgy + self.y) * dv + bv.y;
    if (!LAYER2) { gx = fmaxf(gx, 0.f); gy = fmaxf(gy, 0.f); }
    reinterpret_cast<float2*>(g_bufB)[i * 32 + lane] = make_float2(gx, gy);
    int cnt = end - beg;
    float ic = (cnt > 0) ? (1.f / (float)cnt) : 0.f;
    reinterpret_cast<float2*>(g_bufC)[i * 32 + lane] = make_float2(ssx * ic, ssy * ic);
}

// s1 = relu(mean1@Wl1 + x@Wr1 + bl1) ; hd2 = (g1@gcn_w2) * dinv
__global__ __launch_bounds__(256) void k_mid(const float* __restrict__ x,
                                             const float* __restrict__ wl1,
                                             const float* __restrict__ bl1,
                                             const float* __restrict__ wr1,
                                             const float* __restrict__ gw2, int n) {
    __shared__ alignas(16) float Ws[64][64];
    __shared__ alignas(16) float In[64][65];
    int base = blockIdx.x * 64;
    int tx = threadIdx.x & 15, ty = threadIdx.x >> 4;
    float accS[4][4] = {}, accG[4][4] = {};
    load_w(Ws, wl1); load_in(In, g_bufC, base, n); __syncthreads();
    mm_acc(In, Ws, accS, tx, ty); __syncthreads();
    load_w(Ws, wr1); load_in(In, x, base, n); __syncthreads();
    mm_acc(In, Ws, accS, tx, ty); __syncthreads();
    load_w(Ws, gw2); load_in(In, g_bufB, base, n); __syncthreads();
    mm_acc(In, Ws, accG, tx, ty);
    float4 bv = *reinterpret_cast<const float4*>(bl1 + tx * 4);
#pragma unroll
    for (int i = 0; i < 4; i++) {
        int node = base + ty * 4 + i;
        if (node < n) {
            float dv = g_dinv[node];
            float4 s = make_float4(fmaxf(accS[i][0] + bv.x, 0.f),
                                   fmaxf(accS[i][1] + bv.y, 0.f),
                                   fmaxf(accS[i][2] + bv.z, 0.f),
                                   fmaxf(accS[i][3] + bv.w, 0.f));
            *reinterpret_cast<float4*>(&g_bufD[node * 64 + tx * 4]) = s;
            float4 h = make_float4(accG[i][0] * dv, accG[i][1] * dv,
                                   accG[i][2] * dv, accG[i][3] * dv);
            *reinterpret_cast<float4*>(&g_bufA[node * 64 + tx * 4]) = h;
        }
    }
}

// s2 = mean2@Wl2 + s1@Wr2 + bl2; LN(g2), LN(s2); out = [g2n,s2n]@proj_w + proj_b
__global__ __launch_bounds__(256) void k_fin(
    const float* __restrict__ wl2, const float* __restrict__ bl2,
    const float* __restrict__ wr2,
    const float* __restrict__ gcn_g, const float* __restrict__ gcn_b,
    const float* __restrict__ sag_g, const float* __restrict__ sag_b,
    const float* __restrict__ pw, const float* __restrict__ pb,
    float* __restrict__ out, int n) {
    __shared__ alignas(16) float Ws[64][64];
    __shared__ alignas(16) float In[64][65];
    int base = blockIdx.x * 64;
    int tx = threadIdx.x & 15, ty = threadIdx.x >> 4;

    float accS[4][4] = {};
    load_w(Ws, wl2); load_in(In, g_bufC, base, n); __syncthreads();
    mm_acc(In, Ws, accS, tx, ty); __syncthreads();
    load_w(Ws, wr2); load_in(In, g_bufD, base, n); __syncthreads();
    mm_acc(In, Ws, accS, tx, ty); __syncthreads();

    float4 pbv = *reinterpret_cast<const float4*>(pb + tx * 4);
    float accO[4][4];
#pragma unroll
    for (int i = 0; i < 4; i++) {
        accO[i][0] = pbv.x; accO[i][1] = pbv.y; accO[i][2] = pbv.z; accO[i][3] = pbv.w;
    }

    // GCN branch: LN(g2) then @ proj_w[0:64]
    load_w(Ws, pw); load_in(In, g_bufB, base, n); __syncthreads();
    ln_rows(In, gcn_g, gcn_b); __syncthreads();
    mm_acc(In, Ws, accO, tx, ty); __syncthreads();

    // SAGE branch: stage s2 into smem, LN, then @ proj_w[64:128]
    float4 blv = *reinterpret_cast<const float4*>(bl2 + tx * 4);
#pragma unroll
    for (int i = 0; i < 4; i++) {
        In[ty * 4 + i][tx * 4 + 0] = accS[i][0] + blv.x;
        In[ty * 4 + i][tx * 4 + 1] = accS[i][1] + blv.y;
        In[ty * 4 + i][tx * 4 + 2] = accS[i][2] + blv.z;
        In[ty * 4 + i][tx * 4 + 3] = accS[i][3] + blv.w;
    }
    load_w(Ws, pw + 64 * 64);
    __syncthreads();
    ln_rows(In, sag_g, sag_b); __syncthreads();
    mm_acc(In, Ws, accO, tx, ty);

#pragma unroll
    for (int i = 0; i < 4; i++) {
        int node = base + ty * 4 + i;
        if (node < n) {
            *reinterpret_cast<float4*>(&out[node * 64 + tx * 4]) =
                make_float4(accO[i][0], accO[i][1], accO[i][2], accO[i][3]);
        }
    }
}

// --------------------------------- launch -----------------------------------

extern "C" void kernel_launch(void* const* d_in, const int* in_sizes, int n_in,
                              void* d_out, int out_size) {
    const float* x      = (const float*)d_in[0];
    const void*  ei     = d_in[1];
    const float* gcn_w1 = (const float*)d_in[2];
    const float* gcn_b1 = (const float*)d_in[3];
    const float* gcn_w2 = (const float*)d_in[4];
    const float* gcn_b2 = (const float*)d_in[5];
    const float* wl1    = (const float*)d_in[6];
    const float* bl1    = (const float*)d_in[7];
    const float* wr1    = (const float*)d_in[8];
    const float* wl2    = (const float*)d_in[9];
    const float* bl2    = (const float*)d_in[10];
    const float* wr2    = (const float*)d_in[11];
    const float* lg     = (const float*)d_in[12];
    const float* lb     = (const float*)d_in[13];
    const float* sg     = (const float*)d_in[14];
    const float* sb     = (const float*)d_in[15];
    const float* pw     = (const float*)d_in[16];
    const float* pb     = (const float*)d_in[17];
    float* out = (float*)d_out;

    int n = in_sizes[0] / 64;
    int e = in_sizes[1] / 2;

    int grid64 = (n + 63) / 64;
    int gridE  = (e + 255) / 256;
    int gridP  = (n + 7) / 8;   // warp per node, 8 warps/block

    k_detect<<<1, 256>>>((const unsigned int*)ei, e);
    k_zero<<<(n + 255) / 256, 256>>>(n);
    k_deg<<<gridE, 256>>>(ei, e);
    k_scan<<<1, 1024>>>(n);
    k_fill<<<gridE, 256>>>(ei, e);
    k_h1<<<grid64, 256>>>(x, gcn_w1, n);
    k_pull<false><<<gridP, 256>>>(x, gcn_b1, n);
    k_mid<<<grid64, 256>>>(x, wl1, bl1, wr1, gcn_w2, n);
    k_pull<true><<<gridP, 256>>>(x, gcn_b2, n);
    k_fin<<<grid64, 256>>>(wl2, bl2, wr2, lg, lb, sg, sb, pw, pb, out, n);
}

// round 3
// speedup vs baseline: 1.4239x; 1.4239x over previous
#include <cuda_runtime.h>

// ---------------------------------------------------------------------------
// HybridGCNGraphSAGE: N=100000 nodes, E=1250000 edges, all feature dims = 64.
//
//  - edge_index dtype (int32 vs int64) detected at runtime each call.
//  - Build CSR-by-dst every call (deg -> 3-phase multi-block scan -> bin fill).
//  - PULL aggregation (no float atomics): warp-per-node, fused GCN+SAGE walk.
//  - GCN norm factored: out_i = dinv_i * (sum_{src} hd[src] + hd[i]) + b,
//    with hd = (x@W) * dinv precomputed in the GEMM kernels.
//  - Per-node GEMMs as 64-node x 64-col smem tile kernels (256 thr, 4x4
//    micro-tile), multiple matvec "phases" reusing the same smem.
//  - Final kernel fuses SAGE layer-2 linear + both LayerNorms + concat-proj.
// ---------------------------------------------------------------------------

#define NMAX 100000
#define EMAX 1250000
#define SC   512          // scan chunk per block
#define MAXBLK 256        // max scan blocks (100000/512 = 196)

__device__ int   g_is64;
__device__ int   g_deg[NMAX];
__device__ int   g_rowptr[NMAX + 1];
__device__ int   g_cursor[NMAX];
__device__ int   g_csr[EMAX];
__device__ int   g_bsum[MAXBLK];
__device__ int   g_boff[MAXBLK];
__device__ float g_dinv[NMAX];
__device__ alignas(16) float g_bufA[NMAX * 64];  // hd1, then hd2
__device__ alignas(16) float g_bufB[NMAX * 64];  // g1 (relu'd GCN layer1), then g2
__device__ alignas(16) float g_bufC[NMAX * 64];  // sage mean1, then mean2
__device__ alignas(16) float g_bufD[NMAX * 64];  // s1 (relu'd SAGE layer1)

// --------------------------- dtype detection --------------------------------
// int64 edge values are < 2^31, so every odd 32-bit word of the first 2048
// int64s is zero. int32 edge data puts random node ids there instead.
__global__ void k_detect(const unsigned int* __restrict__ w, int e) {
    __shared__ int any;
    if (threadIdx.x == 0) any = 0;
    __syncthreads();
    int limit = 2 * e; if (limit > 4096) limit = 4096;
    for (int i = 1 + 2 * (int)threadIdx.x; i < limit; i += 2 * blockDim.x)
        if (w[i] != 0u) any = 1;
    __syncthreads();
    if (threadIdx.x == 0) g_is64 = (any == 0) ? 1 : 0;
}

__device__ __forceinline__ int edge_at(const void* ei, int idx) {
    if (g_is64) return (int)((const long long*)ei)[idx];
    return ((const int*)ei)[idx];
}

// ------------------------------- CSR build ---------------------------------

__global__ void k_zero(int n) {
    int i = blockIdx.x * blockDim.x + threadIdx.x;
    if (i < n) g_deg[i] = 0;
}

__global__ void k_deg(const void* __restrict__ ei, int e) {
    int i = blockIdx.x * blockDim.x + threadIdx.x;
    if (i < e) {
        int d = edge_at(ei, e + i);
        atomicAdd(&g_deg[d], 1);
    }
}

// Phase 1: per-block sum of SC degree entries.
__global__ __launch_bounds__(SC) void k_scan1(int n) {
    __shared__ int ws[SC / 32];
    int i = blockIdx.x * SC + threadIdx.x;
    int v = (i < n) ? g_deg[i] : 0;
#pragma unroll
    for (int o = 16; o; o >>= 1) v += __shfl_down_sync(~0u, v, o);
    if ((threadIdx.x & 31) == 0) ws[threadIdx.x >> 5] = v;
    __syncthreads();
    if (threadIdx.x < 32) {
        int s = (threadIdx.x < SC / 32) ? ws[threadIdx.x] : 0;
#pragma unroll
        for (int o = 16; o; o >>= 1) s += __shfl_down_sync(~0u, s, o);
        if (threadIdx.x == 0) g_bsum[blockIdx.x] = s;
    }
}

// Phase 2: single-block exclusive scan over block sums (nblk <= 256).
__global__ __launch_bounds__(MAXBLK) void k_scan2(int nblk, int n) {
    __shared__ int part[MAXBLK];
    int t = threadIdx.x;
    int v = (t < nblk) ? g_bsum[t] : 0;
    part[t] = v;
    __syncthreads();
#pragma unroll
    for (int o = 1; o < MAXBLK; o <<= 1) {
        int u = (t >= o) ? part[t - o] : 0;
        __syncthreads();
        part[t] += u;
        __syncthreads();
    }
    if (t < nblk) g_boff[t] = part[t] - v;
    if (t == 0) g_rowptr[n] = part[MAXBLK - 1];
}

// Phase 3: per-block local exclusive scan + block offset -> rowptr/cursor.
__global__ __launch_bounds__(SC) void k_scan3(int n) {
    __shared__ int part[SC];
    int t = threadIdx.x;
    int i = blockIdx.x * SC + t;
    int v = (i < n) ? g_deg[i] : 0;
    part[t] = v;
    __syncthreads();
#pragma unroll
    for (int o = 1; o < SC; o <<= 1) {
        int u = (t >= o) ? part[t - o] : 0;
        __syncthreads();
        part[t] += u;
        __syncthreads();
    }
    if (i < n) {
        int ex = g_boff[blockIdx.x] + part[t] - v;
        g_rowptr[i] = ex;
        g_cursor[i] = ex;
    }
}

__global__ void k_fill(const void* __restrict__ ei, int e) {
    int i = blockIdx.x * blockDim.x + threadIdx.x;
    if (i < e) {
        int s = edge_at(ei, i);
        int d = edge_at(ei, e + i);
        int pos = atomicAdd(&g_cursor[d], 1);
        g_csr[pos] = s;
    }
}

// ---------------------------- tile GEMM helpers -----------------------------

__device__ __forceinline__ void load_w(float (*Ws)[64], const float* __restrict__ W) {
    float4* d = reinterpret_cast<float4*>(&Ws[0][0]);
    const float4* s = reinterpret_cast<const float4*>(W);
    for (int i = threadIdx.x; i < 1024; i += 256) d[i] = s[i];
}

__device__ __forceinline__ void load_in(float (*In)[65], const float* __restrict__ src,
                                        int base, int n) {
    for (int i = threadIdx.x; i < 1024; i += 256) {
        int r = i >> 4, c = (i & 15) << 2;
        float4 v = make_float4(0.f, 0.f, 0.f, 0.f);
        int node = base + r;
        if (node < n) v = *reinterpret_cast<const float4*>(src + node * 64 + c);
        In[r][c] = v.x; In[r][c + 1] = v.y; In[r][c + 2] = v.z; In[r][c + 3] = v.w;
    }
}

__device__ __forceinline__ void mm_acc(float (*In)[65], float (*Ws)[64],
                                       float acc[4][4], int tx, int ty) {
#pragma unroll 8
    for (int k = 0; k < 64; k++) {
        float a0 = In[ty * 4 + 0][k];
        float a1 = In[ty * 4 + 1][k];
        float a2 = In[ty * 4 + 2][k];
        float a3 = In[ty * 4 + 3][k];
        float4 w = *reinterpret_cast<float4*>(&Ws[k][tx * 4]);
        acc[0][0] += a0 * w.x; acc[0][1] += a0 * w.y; acc[0][2] += a0 * w.z; acc[0][3] += a0 * w.w;
        acc[1][0] += a1 * w.x; acc[1][1] += a1 * w.y; acc[1][2] += a1 * w.z; acc[1][3] += a1 * w.w;
        acc[2][0] += a2 * w.x; acc[2][1] += a2 * w.y; acc[2][2] += a2 * w.z; acc[2][3] += a2 * w.w;
        acc[3][0] += a3 * w.x; acc[3][1] += a3 * w.y; acc[3][2] += a3 * w.z; acc[3][3] += a3 * w.w;
    }
}

__device__ __forceinline__ void ln_rows(float (*In)[65], const float* __restrict__ gma,
                                        const float* __restrict__ bta) {
    int t = threadIdx.x;
    if (t < 64) {
        float s = 0.f, sq = 0.f;
#pragma unroll 8
        for (int k = 0; k < 64; k++) { float v = In[t][k]; s += v; sq += v * v; }
        float mu = s * 0.015625f;
        float var = sq * 0.015625f - mu * mu;
        float rs = rsqrtf(var + 1e-5f);
#pragma unroll 8
        for (int k = 0; k < 64; k++) In[t][k] = (In[t][k] - mu) * rs * gma[k] + bta[k];
    }
}

// hd1 = (x @ gcn_w1) * dinv   ; also materialize dinv[]
__global__ __launch_bounds__(256) void k_h1(const float* __restrict__ x,
                                            const float* __restrict__ w1, int n) {
    __shared__ alignas(16) float Ws[64][64];
    __shared__ alignas(16) float In[64][65];
    int base = blockIdx.x * 64;
    load_w(Ws, w1);
    load_in(In, x, base, n);
    __syncthreads();
    int tx = threadIdx.x & 15, ty = threadIdx.x >> 4;
    float acc[4][4] = {};
    mm_acc(In, Ws, acc, tx, ty);
#pragma unroll
    for (int i = 0; i < 4; i++) {
        int node = base + ty * 4 + i;
        if (node < n) {
            float dv = rsqrtf((float)g_deg[node] + 1.f);
            if (tx == 0) g_dinv[node] = dv;
            float4 v = make_float4(acc[i][0] * dv, acc[i][1] * dv, acc[i][2] * dv, acc[i][3] * dv);
            *reinterpret_cast<float4*>(&g_bufA[node * 64 + tx * 4]) = v;
        }
    }
}

// Fused pull aggregation (GCN + SAGE share the edge walk), warp-per-node.
template <bool LAYER2>
__global__ __launch_bounds__(256) void k_pull(const float* __restrict__ xsrc,
                                              const float* __restrict__ bias, int n) {
    int lane = threadIdx.x & 31;
    int i = (blockIdx.x * 256 + threadIdx.x) >> 5;
    if (i >= n) return;
    const float2* __restrict__ tg = reinterpret_cast<const float2*>(g_bufA);
    const float2* __restrict__ ts = LAYER2 ? reinterpret_cast<const float2*>(g_bufD)
                                           : reinterpret_cast<const float2*>(xsrc);
    int beg = g_rowptr[i], end = g_rowptr[i + 1];
    float sgx = 0.f, sgy = 0.f, ssx = 0.f, ssy = 0.f;
    int e = beg;
    for (; e + 2 <= end; e += 2) {
        int s0 = g_csr[e], s1 = g_csr[e + 1];
        float2 h0 = tg[s0 * 32 + lane];
        float2 h1 = tg[s1 * 32 + lane];
        float2 x0 = ts[s0 * 32 + lane];
        float2 x1 = ts[s1 * 32 + lane];
        sgx += h0.x + h1.x; sgy += h0.y + h1.y;
        ssx += x0.x + x1.x; ssy += x0.y + x1.y;
    }
    if (e < end) {
        int s0 = g_csr[e];
        float2 h0 = tg[s0 * 32 + lane];
        float2 x0 = ts[s0 * 32 + lane];
        sgx += h0.x; sgy += h0.y; ssx += x0.x; ssy += x0.y;
    }
    float dv = g_dinv[i];
    float2 self = tg[i * 32 + lane];
    float2 bv = reinterpret_cast<const float2*>(bias)[lane];
    float gx = (sgx + self.x) * dv + bv.x;
    float gy = (sgy + self.y) * dv + bv.y;
    if (!LAYER2) { gx = fmaxf(gx, 0.f); gy = fmaxf(gy, 0.f); }
    reinterpret_cast<float2*>(g_bufB)[i * 32 + lane] = make_float2(gx, gy);
    int cnt = end - beg;
    float ic = (cnt > 0) ? (1.f / (float)cnt) : 0.f;
    reinterpret_cast<float2*>(g_bufC)[i * 32 + lane] = make_float2(ssx * ic, ssy * ic);
}

// s1 = relu(mean1@Wl1 + x@Wr1 + bl1) ; hd2 = (g1@gcn_w2) * dinv
__global__ __launch_bounds__(256) void k_mid(const float* __restrict__ x,
                                             const float* __restrict__ wl1,
                                             const float* __restrict__ bl1,
                                             const float* __restrict__ wr1,
                                             const float* __restrict__ gw2, int n) {
    __shared__ alignas(16) float Ws[64][64];
    __shared__ alignas(16) float In[64][65];
    int base = blockIdx.x * 64;
    int tx = threadIdx.x & 15, ty = threadIdx.x >> 4;
    float accS[4][4] = {}, accG[4][4] = {};
    load_w(Ws, wl1); load_in(In, g_bufC, base, n); __syncthreads();
    mm_acc(In, Ws, accS, tx, ty); __syncthreads();
    load_w(Ws, wr1); load_in(In, x, base, n); __syncthreads();
    mm_acc(In, Ws, accS, tx, ty); __syncthreads();
    load_w(Ws, gw2); load_in(In, g_bufB, base, n); __syncthreads();
    mm_acc(In, Ws, accG, tx, ty);
    float4 bv = *reinterpret_cast<const float4*>(bl1 + tx * 4);
#pragma unroll
    for (int i = 0; i < 4; i++) {
        int node = base + ty * 4 + i;
        if (node < n) {
            float dv = g_dinv[node];
            float4 s = make_float4(fmaxf(accS[i][0] + bv.x, 0.f),
                                   fmaxf(accS[i][1] + bv.y, 0.f),
                                   fmaxf(accS[i][2] + bv.z, 0.f),
                                   fmaxf(accS[i][3] + bv.w, 0.f));
            *reinterpret_cast<float4*>(&g_bufD[node * 64 + tx * 4]) = s;
            float4 h = make_float4(accG[i][0] * dv, accG[i][1] * dv,
                                   accG[i][2] * dv, accG[i][3] * dv);
            *reinterpret_cast<float4*>(&g_bufA[node * 64 + tx * 4]) = h;
        }
    }
}

// s2 = mean2@Wl2 + s1@Wr2 + bl2; LN(g2), LN(s2); out = [g2n,s2n]@proj_w + proj_b
__global__ __launch_bounds__(256) void k_fin(
    const float* __restrict__ wl2, const float* __restrict__ bl2,
    const float* __restrict__ wr2,
    const float* __restrict__ gcn_g, const float* __restrict__ gcn_b,
    const float* __restrict__ sag_g, const float* __restrict__ sag_b,
    const float* __restrict__ pw, const float* __restrict__ pb,
    float* __restrict__ out, int n) {
    __shared__ alignas(16) float Ws[64][64];
    __shared__ alignas(16) float In[64][65];
    int base = blockIdx.x * 64;
    int tx = threadIdx.x & 15, ty = threadIdx.x >> 4;

    float accS[4][4] = {};
    load_w(Ws, wl2); load_in(In, g_bufC, base, n); __syncthreads();
    mm_acc(In, Ws, accS, tx, ty); __syncthreads();
    load_w(Ws, wr2); load_in(In, g_bufD, base, n); __syncthreads();
    mm_acc(In, Ws, accS, tx, ty); __syncthreads();

    float4 pbv = *reinterpret_cast<const float4*>(pb + tx * 4);
    float accO[4][4];
#pragma unroll
    for (int i = 0; i < 4; i++) {
        accO[i][0] = pbv.x; accO[i][1] = pbv.y; accO[i][2] = pbv.z; accO[i][3] = pbv.w;
    }

    // GCN branch: LN(g2) then @ proj_w[0:64]
    load_w(Ws, pw); load_in(In, g_bufB, base, n); __syncthreads();
    ln_rows(In, gcn_g, gcn_b); __syncthreads();
    mm_acc(In, Ws, accO, tx, ty); __syncthreads();

    // SAGE branch: stage s2 into smem, LN, then @ proj_w[64:128]
    float4 blv = *reinterpret_cast<const float4*>(bl2 + tx * 4);
#pragma unroll
    for (int i = 0; i < 4; i++) {
        In[ty * 4 + i][tx * 4 + 0] = accS[i][0] + blv.x;
        In[ty * 4 + i][tx * 4 + 1] = accS[i][1] + blv.y;
        In[ty * 4 + i][tx * 4 + 2] = accS[i][2] + blv.z;
        In[ty * 4 + i][tx * 4 + 3] = accS[i][3] + blv.w;
    }
    load_w(Ws, pw + 64 * 64);
    __syncthreads();
    ln_rows(In, sag_g, sag_b); __syncthreads();
    mm_acc(In, Ws, accO, tx, ty);

#pragma unroll
    for (int i = 0; i < 4; i++) {
        int node = base + ty * 4 + i;
        if (node < n) {
            *reinterpret_cast<float4*>(&out[node * 64 + tx * 4]) =
                make_float4(accO[i][0], accO[i][1], accO[i][2], accO[i][3]);
        }
    }
}

// --------------------------------- launch -----------------------------------

extern "C" void kernel_launch(void* const* d_in, const int* in_sizes, int n_in,
                              void* d_out, int out_size) {
    const float* x      = (const float*)d_in[0];
    const void*  ei     = d_in[1];
    const float* gcn_w1 = (const float*)d_in[2];
    const float* gcn_b1 = (const float*)d_in[3];
    const float* gcn_w2 = (const float*)d_in[4];
    const float* gcn_b2 = (const float*)d_in[5];
    const float* wl1    = (const float*)d_in[6];
    const float* bl1    = (const float*)d_in[7];
    const float* wr1    = (const float*)d_in[8];
    const float* wl2    = (const float*)d_in[9];
    const float* bl2    = (const float*)d_in[10];
    const float* wr2    = (const float*)d_in[11];
    const float* lg     = (const float*)d_in[12];
    const float* lb     = (const float*)d_in[13];
    const float* sg     = (const float*)d_in[14];
    const float* sb     = (const float*)d_in[15];
    const float* pw     = (const float*)d_in[16];
    const float* pb     = (const float*)d_in[17];
    float* out = (float*)d_out;

    int n = in_sizes[0] / 64;
    int e = in_sizes[1] / 2;

    int grid64 = (n + 63) / 64;
    int gridE  = (e + 255) / 256;
    int gridP  = (n + 7) / 8;   // warp per node, 8 warps/block
    int nblk   = (n + SC - 1) / SC;

    k_detect<<<1, 256>>>((const unsigned int*)ei, e);
    k_zero<<<(n + 255) / 256, 256>>>(n);
    k_deg<<<gridE, 256>>>(ei, e);
    k_scan1<<<nblk, SC>>>(n);
    k_scan2<<<1, MAXBLK>>>(nblk, n);
    k_scan3<<<nblk, SC>>>(n);
    k_fill<<<gridE, 256>>>(ei, e);
    k_h1<<<grid64, 256>>>(x, gcn_w1, n);
    k_pull<false><<<gridP, 256>>>(x, gcn_b1, n);
    k_mid<<<grid64, 256>>>(x, wl1, bl1, wr1, gcn_w2, n);
    k_pull<true><<<gridP, 256>>>(x, gcn_b2, n);
    k_fin<<<grid64, 256>>>(wl2, bl2, wr2, lg, lb, sg, sb, pw, pb, out, n);
}